// round 8
// baseline (speedup 1.0000x reference)
#include <cuda_runtime.h>
#include <cstdint>

#define OH 7
#define OW 7
#define CC 8           // channels per block (== warps per block)
#define NROWS 14       // 2 corner rows per output row
#define NF4 17         // max float4 chunks per staged row
#define WPADF (NF4*4)  // 68 floats per staged row
#define PSTRIDE 64     // ints per roi param record (256B)
#define MAXROIS 2048

__device__ int g_params[MAXROIS * PSTRIDE];   // static scratch (no alloc)

// ---- per-RoI parameter precompute: one thread per RoI ----
__global__ void precompute_kernel(const int* __restrict__ rois, int N,
                                  int C, int H, int W) {
    const int t = blockIdx.x * blockDim.x + threadIdx.x;
    if (t >= N) return;
    const int* r = rois + t * 5;
    const int b = r[0], x1 = r[1], y1 = r[2], x2 = r[3], y2 = r[4];

    const int xlo4 = x1 & ~3;
    const int xhi  = min(x2 + 1, W - 1);
    const int nf4  = min((xhi - xlo4 + 4) >> 2, (W - xlo4) >> 2);

    const float dy6 = (float)(y2 - y1) * 0.16666667f;
    const float dx6 = (float)(x2 - x1) * 0.16666667f;
    const float y1f = (float)y1, x1f = (float)x1;

    int* p = g_params + t * PSTRIDE;

    // header [0..3]: baseoff (long long), nf4
    const long long baseoff = (long long)b * C * H * W + xlo4;
    *(long long*)p = baseoff;
    p[2] = nf4;
    p[3] = 0;

    // oxp[8] at [4..35]: {xa, xb, bits(wx), 0} per output-x (entry 7 zero)
    #pragma unroll
    for (int j = 0; j < 7; j++) {
        float sxv = x1f + (float)j * dx6;
        float x0f = floorf(sxv);
        int ix0 = (int)x0f;                 // sx in [x1,x2] >= 0 -> trunc == floor
        int ix1 = min(ix0 + 1, W - 1);
        p[4 + 4*j + 0] = ix0 - xlo4;
        p[4 + 4*j + 1] = ix1 - xlo4;
        p[4 + 4*j + 2] = __float_as_int(sxv - x0f);
        p[4 + 4*j + 3] = 0;
    }
    p[32] = p[33] = p[34] = p[35] = 0;

    // y rows + weights
    float wy[7]; int ro0[7], ro1[7];
    #pragma unroll
    for (int j = 0; j < 7; j++) {
        float syv = y1f + (float)j * dy6;
        float y0f = floorf(syv);
        int iy0 = (int)y0f;
        int iy1 = min(iy0 + 1, H - 1);
        wy[j]  = syv - y0f;
        ro0[j] = iy0 * W;
        ro1[j] = iy1 * W;
    }
    // wyp[4] float2 at [36..43]: (wy[k], wy[k+4])
    #pragma unroll
    for (int k = 0; k < 4; k++) {
        p[36 + 2*k]     = __float_as_int(wy[k]);
        p[36 + 2*k + 1] = __float_as_int((k + 4 < 7) ? wy[k + 4] : 0.0f);
    }
    // rowoff[14] at [44..57]: rows 0..6 = y0 rows, 7..13 = y1 rows
    #pragma unroll
    for (int j = 0; j < 7; j++) { p[44 + j] = ro0[j]; p[51 + j] = ro1[j]; }
}

// ---- main kernel: params preloaded, warp = channel ----
__global__ void roialign_kernel(const float* __restrict__ feat,
                                float* __restrict__ out,
                                int C, int H, int W) {
    __shared__ __align__(16) float s[CC * NROWS * WPADF];   // 30464 B

    const int n    = blockIdx.x;
    const int c0   = blockIdx.y * CC;
    const int tid  = threadIdx.x;
    const int warp = tid >> 5, lane = tid & 31;

    const int* p = g_params + n * PSTRIDE;

    const long long baseoff = __ldg((const long long*)p);      // uniform
    const int nf4           = __ldg(p + 2);                    // uniform
    const int4   oxp = __ldg((const int4*)(p + 4) + (lane & 7));
    const float2 wyp = __ldg((const float2*)(p + 36) + (lane >> 3));
    const int myrowoff = (lane < NROWS) ? __ldg(p + 44 + lane) : 0;

    // ---- stage via cp.async: warp = channel, 16 lanes x 2 rows per step ----
    const float* gbase = feat + baseoff + (size_t)(c0 + warp) * (size_t)(H * W);
    float* sbase = s + warp * (NROWS * WPADF);
    {
        const int i4   = lane & 15;
        const int rsel = lane >> 4;
        const bool needme = i4 < nf4;
        #pragma unroll
        for (int rp = 0; rp < 7; rp++) {
            const int row    = 2 * rp + rsel;
            const int rowoff = __shfl_sync(0xffffffffu, myrowoff, row);
            const float* src = gbase + rowoff + i4 * 4;
            const uint32_t dst =
                (uint32_t)__cvta_generic_to_shared(sbase + row * WPADF + i4 * 4);
            if (needme)
                asm volatile("cp.async.cg.shared.global [%0], [%1], 16;\n"
                             :: "r"(dst), "l"(src));
        }
        if (nf4 > 16) {  // rare 17th chunk
            const float* src = gbase + myrowoff + 64;
            const uint32_t dst =
                (uint32_t)__cvta_generic_to_shared(sbase + lane * WPADF + 64);
            if (lane < NROWS)
                asm volatile("cp.async.cg.shared.global [%0], [%1], 16;\n"
                             :: "r"(dst), "l"(src));
        }
        asm volatile("cp.async.commit_group;\n" ::: "memory");
        asm volatile("cp.async.wait_group 0;\n" ::: "memory");
        __syncwarp();
    }

    // ---- compute: per-lane x params from table, 8-padded mapping ----
    const int   ox  = lane & 7;
    const int   xa  = oxp.x, xb = oxp.y;
    const float wx  = __int_as_float(oxp.z);
    const float omx = 1.0f - wx;

    float* obase = out + ((size_t)(n * C + c0 + warp)) * (OH * OW);
    {
        const int oy = lane >> 3;               // 0..3
        if (ox < OW) {
            const float wy  = wyp.x;
            const float omy = 1.0f - wy;
            const float* p0 = sbase + oy * WPADF;
            const float* p1 = p0 + OH * WPADF;
            const float v00 = p0[xa], v01 = p0[xb];
            const float v10 = p1[xa], v11 = p1[xb];
            obase[oy * OW + ox] =
                (v00 * omx + v01 * wx) * omy + (v10 * omx + v11 * wx) * wy;
        }
    }
    {
        const int oy = (lane >> 3) + 4;         // 4..7
        if (ox < OW && oy < OH) {
            const float wy  = wyp.y;
            const float omy = 1.0f - wy;
            const float* p0 = sbase + oy * WPADF;
            const float* p1 = p0 + OH * WPADF;
            const float v00 = p0[xa], v01 = p0[xb];
            const float v10 = p1[xa], v11 = p1[xb];
            obase[oy * OW + ox] =
                (v00 * omx + v01 * wx) * omy + (v10 * omx + v11 * wx) * wy;
        }
    }
}

extern "C" void kernel_launch(void* const* d_in, const int* in_sizes, int n_in,
                              void* d_out, int out_size) {
    const float* feat = (const float*)d_in[0];
    const int*   rois = (const int*)d_in[1];
    float*       out  = (float*)d_out;

    const int C = 256, H = 200, W = 200;
    const int N = in_sizes[1] / 5;

    precompute_kernel<<<(N + 255) / 256, 256>>>(rois, N, C, H, W);

    dim3 grid(N, C / CC);
    roialign_kernel<<<grid, 256>>>(feat, out, C, H, W);
}

// round 9
// speedup vs baseline: 1.2305x; 1.2305x over previous
#include <cuda_runtime.h>
#include <cstdint>

#define OH 7
#define OW 7
#define CC 4            // warps per block
#define CH 4            // channels per warp (pipelined)
#define NROWS 14        // 2 corner rows per output row
#define NF4 17          // max float4 chunks per staged row
#define WPADF (NF4*4)   // 68 floats per staged row
#define BUFSZ (NROWS*WPADF)   // floats per buffer (3808 B)

__global__ void __launch_bounds__(128) roialign_kernel(
        const float* __restrict__ feat,
        const int* __restrict__ rois,
        float* __restrict__ out,
        int C, int H, int W) {
    __shared__ __align__(16) float s[CC * 2 * BUFSZ];   // 30464 B

    const int n    = blockIdx.x;
    const int cg   = blockIdx.y;              // channel group of CC*CH channels
    const int tid  = threadIdx.x;
    const int warp = tid >> 5, lane = tid & 31;
    const int cbase = (cg * CC + warp) * CH;  // first channel for this warp

    const int* r = rois + n * 5;
    const int b  = __ldg(r);
    const int x1 = __ldg(r + 1), y1 = __ldg(r + 2);
    const int x2 = __ldg(r + 3), y2 = __ldg(r + 4);

    const int xlo4 = x1 & ~3;
    const int xhi  = min(x2 + 1, W - 1);
    const int nf4  = min((xhi - xlo4 + 4) >> 2, (W - xlo4) >> 2);

    const float dy6 = (float)(y2 - y1) * 0.16666667f;
    const float dx6 = (float)(x2 - x1) * 0.16666667f;
    const float y1f = (float)y1, x1f = (float)x1;

    // per-lane staged-row offset: lanes 0..6 -> y0 rows, lanes 7..13 -> y1 rows
    int myrowoff;
    {
        const int jj = (lane < 7) ? lane : lane - 7;
        float sy  = y1f + (float)jj * dy6;
        int   iy0 = (int)sy;                  // sy in [y1,y2] >= 0: trunc == floor
        int   iy1 = min(iy0 + 1, H - 1);
        myrowoff = ((lane < 7) ? iy0 : iy1) * W;
    }

    // hoisted per-lane x params (fixed per lane, 8-padded mapping)
    const int ox = lane & 7;
    float sx  = x1f + (float)ox * dx6;
    float x0f = floorf(sx);
    const float wx  = sx - x0f;
    const float omx = 1.0f - wx;
    int ix0 = (int)x0f;                       // in [x1,x2], no clamp needed
    int ix1 = min(ix0 + 1, W - 1);
    const int xa = ix0 - xlo4;
    const int xb = ix1 - xlo4;

    // y weights for the two compute halves (oy = lane>>3 and +4)
    const int oyA = lane >> 3;                // 0..3
    const int oyB = oyA + 4;                  // 4..7 (7 masked)
    float syA = y1f + (float)oyA * dy6;
    float syB = y1f + (float)oyB * dy6;
    const float wyA = syA - floorf(syA);
    const float wyB = syB - floorf(syB);
    const float omyA = 1.0f - wyA;
    const float omyB = 1.0f - wyB;

    const size_t HW = (size_t)(H * W);
    const float* gch = feat + ((size_t)b * C + cbase) * HW + xlo4;
    float* sbase = s + warp * (2 * BUFSZ);
    float* obase = out + ((size_t)(n * C + cbase)) * (OH * OW);

    const int i4   = lane & 15;
    const int rsel = lane >> 4;
    const bool needme = i4 < nf4;
    const bool extra  = (nf4 > 16) && (lane < NROWS);

    // ---- staging macro-equivalent lambda ----
    auto stage = [&](int k, float* buf) {
        const float* g = gch + (size_t)k * HW;
        #pragma unroll
        for (int rp = 0; rp < 7; rp++) {
            const int row    = 2 * rp + rsel;
            const int rowoff = __shfl_sync(0xffffffffu, myrowoff, row);
            const float* src = g + rowoff + i4 * 4;
            const uint32_t dst =
                (uint32_t)__cvta_generic_to_shared(buf + row * WPADF + i4 * 4);
            if (needme)
                asm volatile("cp.async.cg.shared.global [%0], [%1], 16;\n"
                             :: "r"(dst), "l"(src));
        }
        if (extra) {   // rare 17th chunk: lanes 0..13, row = lane
            const float* src = g + myrowoff + 64;
            const uint32_t dst =
                (uint32_t)__cvta_generic_to_shared(buf + lane * WPADF + 64);
            asm volatile("cp.async.cg.shared.global [%0], [%1], 16;\n"
                         :: "r"(dst), "l"(src));
        }
        asm volatile("cp.async.commit_group;\n" ::: "memory");
    };

    auto compute = [&](int k, const float* buf) {
        float* o = obase + k * (OH * OW);
        if (ox < OW) {
            {
                const float* p0 = buf + oyA * WPADF;
                const float* p1 = p0 + OH * WPADF;
                const float v00 = p0[xa], v01 = p0[xb];
                const float v10 = p1[xa], v11 = p1[xb];
                o[oyA * OW + ox] =
                    (v00 * omx + v01 * wx) * omyA + (v10 * omx + v11 * wx) * wyA;
            }
            if (oyB < OH) {
                const float* p0 = buf + oyB * WPADF;
                const float* p1 = p0 + OH * WPADF;
                const float v00 = p0[xa], v01 = p0[xb];
                const float v10 = p1[xa], v11 = p1[xb];
                o[oyB * OW + ox] =
                    (v00 * omx + v01 * wx) * omyB + (v10 * omx + v11 * wx) * wyB;
            }
        }
    };

    // ---- software pipeline: 2 buffers, CH chunks ----
    stage(0, sbase);
    stage(1, sbase + BUFSZ);

    #pragma unroll
    for (int k = 0; k < CH; k++) {
        if (k < CH - 1) {
            asm volatile("cp.async.wait_group 1;\n" ::: "memory");
        } else {
            asm volatile("cp.async.wait_group 0;\n" ::: "memory");
        }
        __syncwarp();
        float* buf = sbase + (k & 1) * BUFSZ;
        compute(k, buf);
        if (k + 2 < CH) stage(k + 2, buf);
    }
}

extern "C" void kernel_launch(void* const* d_in, const int* in_sizes, int n_in,
                              void* d_out, int out_size) {
    const float* feat = (const float*)d_in[0];
    const int*   rois = (const int*)d_in[1];
    float*       out  = (float*)d_out;

    const int C = 256, H = 200, W = 200;
    const int N = in_sizes[1] / 5;

    dim3 grid(N, C / (CC * CH));
    roialign_kernel<<<grid, CC * 32>>>(feat, rois, out, C, H, W);
}

// round 10
// speedup vs baseline: 1.2665x; 1.0292x over previous
#include <cuda_runtime.h>
#include <cstdint>

#define OH 7
#define OW 7
#define NW 8            // warps per block
#define CH 8            // channels per warp

__global__ void __launch_bounds__(256, 6) roialign_kernel(
        const float* __restrict__ feat,
        const int* __restrict__ rois,
        float* __restrict__ out,
        int C, int H, int W) {
    const int n    = blockIdx.x;
    const int cg   = blockIdx.y;
    const int tid  = threadIdx.x;
    const int warp = tid >> 5, lane = tid & 31;
    const int cbase = (cg * NW + warp) * CH;

    const int* r = rois + n * 5;
    const int b  = __ldg(r);
    const int x1 = __ldg(r + 1), y1 = __ldg(r + 2);
    const int x2 = __ldg(r + 3), y2 = __ldg(r + 4);

    const float dy6 = (float)(y2 - y1) * 0.16666667f;
    const float dx6 = (float)(x2 - x1) * 0.16666667f;
    const float y1f = (float)y1, x1f = (float)x1;

    // ---- per-lane constants: lane = (oy, ox) on an 8x8 padded grid ----
    const int ox  = lane & 7;                 // 0..7 (7 = inactive pad)
    const int oyA = lane >> 3;                // 0..3
    const int oyB = oyA + 4;                  // 4..7 (7 = inactive pad)

    // x corners + weight (clamped; pad lanes get safe in-range addresses)
    float sx  = x1f + (float)ox * dx6;
    float x0f = floorf(sx);
    const float wx  = sx - x0f;
    const float omx = 1.0f - wx;
    int ix0 = min(max((int)x0f, 0), W - 1);
    int ix1 = min(ix0 + 1, W - 1);

    // y rows + weights for both halves (clamped for pad lane oyB==7)
    float syA = y1f + (float)oyA * dy6;
    float syB = y1f + (float)oyB * dy6;
    float yA0f = floorf(syA), yB0f = floorf(syB);
    const float wyA = syA - yA0f, wyB = syB - yB0f;
    const float omyA = 1.0f - wyA, omyB = 1.0f - wyB;
    int iyA0 = min(max((int)yA0f, 0), H - 1);
    int iyA1 = min(iyA0 + 1, H - 1);
    int iyB0 = min(max((int)yB0f, 0), H - 1);
    int iyB1 = min(iyB0 + 1, H - 1);

    // 8 fixed per-lane gather offsets
    const int oA00 = iyA0 * W + ix0, oA01 = iyA0 * W + ix1;
    const int oA10 = iyA1 * W + ix0, oA11 = iyA1 * W + ix1;
    const int oB00 = iyB0 * W + ix0, oB01 = iyB0 * W + ix1;
    const int oB10 = iyB1 * W + ix0, oB11 = iyB1 * W + ix1;

    const size_t HW = (size_t)(H * W);
    const float* g  = feat + ((size_t)b * C + cbase) * HW;
    float* obase    = out + ((size_t)(n * C + cbase)) * (OH * OW);

    const bool actA = (ox < OW);
    const bool actB = (ox < OW) && (oyB < OH);

    #pragma unroll
    for (int k = 0; k < CH; k++) {
        const float* gk = g + (size_t)k * HW;
        // 8 independent loads (full MLP)
        const float a00 = __ldg(gk + oA00);
        const float a01 = __ldg(gk + oA01);
        const float a10 = __ldg(gk + oA10);
        const float a11 = __ldg(gk + oA11);
        const float b00 = __ldg(gk + oB00);
        const float b01 = __ldg(gk + oB01);
        const float b10 = __ldg(gk + oB10);
        const float b11 = __ldg(gk + oB11);

        float* o = obase + k * (OH * OW);
        if (actA)
            o[oyA * OW + ox] = (a00 * omx + a01 * wx) * omyA
                             + (a10 * omx + a11 * wx) * wyA;
        if (actB)
            o[oyB * OW + ox] = (b00 * omx + b01 * wx) * omyB
                             + (b10 * omx + b11 * wx) * wyB;
    }
}

extern "C" void kernel_launch(void* const* d_in, const int* in_sizes, int n_in,
                              void* d_out, int out_size) {
    const float* feat = (const float*)d_in[0];
    const int*   rois = (const int*)d_in[1];
    float*       out  = (float*)d_out;

    const int C = 256, H = 200, W = 200;
    const int N = in_sizes[1] / 5;

    dim3 grid(N, C / (NW * CH));
    roialign_kernel<<<grid, NW * 32>>>(feat, rois, out, C, H, W);
}